// round 16
// baseline (speedup 1.0000x reference)
#include <cuda_runtime.h>
#include <cstdint>
#include <cstddef>

namespace {
constexpr int kM = 64;
constexpr int kK = 4096;
constexpr int kN = 14336;
constexpr int kBN = 16;               // tile width
constexpr int kBK = 128;              // one quant group per chunk
constexpr int kSplit = 2;             // K-split -> finer work quantum
constexpr int kKper = kK / kSplit;    // 2048 (int32 elements of x/q per split)
constexpr int kChunks = kKper / kBK;  // 16 chunks per CTA
constexpr int kTiles = kN / kBN;      // 896 -> grid 1792
constexpr int kPad = 144;             // smem row stride (conflict-free ldmatrix)
constexpr int kAStage = 64 * kPad;    // 9216 B
constexpr int kBStage = kBN * kPad;   // 2304 B
constexpr int kThreads = 256;
}

// device-global scratch (no allocations allowed)
__device__ __align__(16) int8_t g_x8[kM * kK];       // packed int8 activations
__device__ __align__(16) int g_part[kSplit][kM * kN];  // int32 split partials

__global__ void pack_x_kernel(const int* __restrict__ x) {
    int idx = blockIdx.x * blockDim.x + threadIdx.x;  // int4 index over M*K/4
    int4 v = __ldg(((const int4*)x) + idx);
    uint32_t w = (uint32_t)(v.x & 0xff) | ((uint32_t)(v.y & 0xff) << 8)
               | ((uint32_t)(v.z & 0xff) << 16) | ((uint32_t)(v.w & 0xff) << 24);
    ((uint32_t*)g_x8)[idx] = w;
}

// ---------------- PTX helpers ----------------
__device__ __forceinline__ uint32_t smem_u32(const void* p) {
    return (uint32_t)__cvta_generic_to_shared(p);
}
__device__ __forceinline__ void cp_async16(uint32_t dst, const void* src) {
    asm volatile("cp.async.ca.shared.global [%0], [%1], 16;\n" :: "r"(dst), "l"(src));
}
__device__ __forceinline__ void cp_commit() { asm volatile("cp.async.commit_group;\n"); }
__device__ __forceinline__ void cp_wait_all() { asm volatile("cp.async.wait_group 0;\n" ::: "memory"); }
__device__ __forceinline__ uint32_t prmt(uint32_t a, uint32_t b, uint32_t sel) {
    uint32_t d;
    asm("prmt.b32 %0, %1, %2, %3;" : "=r"(d) : "r"(a), "r"(b), "r"(sel));
    return d;
}
__device__ __forceinline__ void ldmatrix_x4(uint32_t r[4], uint32_t addr) {
    asm volatile("ldmatrix.sync.aligned.m8n8.x4.shared.b16 {%0,%1,%2,%3}, [%4];"
                 : "=r"(r[0]), "=r"(r[1]), "=r"(r[2]), "=r"(r[3]) : "r"(addr));
}
__device__ __forceinline__ void mma_s8(int c[4], uint32_t a0, uint32_t a1, uint32_t a2,
                                       uint32_t a3, uint32_t b0, uint32_t b1) {
    asm volatile(
        "mma.sync.aligned.m16n8k32.row.col.s32.s8.s8.s32 "
        "{%0,%1,%2,%3}, {%4,%5,%6,%7}, {%8,%9}, {%0,%1,%2,%3};\n"
        : "+r"(c[0]), "+r"(c[1]), "+r"(c[2]), "+r"(c[3])
        : "r"(a0), "r"(a1), "r"(a2), "r"(a3), "r"(b0), "r"(b1));
}

// ---- cooperative GEMM: R15 verbatim, single delta = occ 6 (regs <= 42) ----
__global__ void __launch_bounds__(kThreads, 6)
w4a8_gemm(const int* __restrict__ qweight,
          const int* __restrict__ s2_scales,
          const int* __restrict__ s2_zeros) {
    __shared__ __align__(16) int8_t As[2][kAStage];
    __shared__ __align__(16) int8_t Bs[2][kBStage];

    const int tid = threadIdx.x;
    const int warp = tid >> 5;
    const int lane = tid & 31;
    const int tile = blockIdx.x >> 1;
    const int split = blockIdx.x & 1;
    const int n0 = tile * kBN;
    const int grp0 = split * kChunks;          // first quant group of this split

    // ---- producer mapping: 16 rows x 16 segments (8 values each) ----
    const int nl = tid >> 4;           // 0..15 weight row in tile
    const int seg = tid & 15;          // 8-value segment within the 128-wide chunk
    const int n_glob = n0 + nl;
    // uniform split base: kKper int32 = kKper/4 int4 units
    const int4* qrow = (const int4*)qweight + (size_t)n_glob * (kK / 4)
                       + split * (kKper / 4);

    // depth-2 register prefetch: chunk j lives in slot j&1
    int4 qv0[2], qv1[2];
    int s2r[2], zr[2];

    auto ldg_chunk = [&](int c) {
        const int b = c & 1;
        qv0[b] = __ldcs(qrow + c * 32 + seg * 2);
        qv1[b] = __ldcs(qrow + c * 32 + seg * 2 + 1);
        s2r[b] = __ldg(s2_scales + (grp0 + c) * kN + n_glob);
        zr[b]  = __ldg(s2_zeros + (grp0 + c) * kN + n_glob);
    };
    auto cp_a = [&](int c, int s) {
#pragma unroll
        for (int j = 0; j < 2; ++j) {
            int id = tid + kThreads * j;           // 0..511
            int row = id >> 3, sg = id & 7;
            cp_async16(smem_u32(&As[s][row * kPad + sg * 16]),
                       g_x8 + (size_t)row * kK + split * kKper + c * kBK + sg * 16);
        }
        cp_commit();
    };
    auto dequant_sts = [&](int c, int s) {
        const int b = c & 1;
        const int sc = s2r[b], zc = zr[b];
        int b0 = qv0[b].x * sc + zc, b1 = qv0[b].y * sc + zc;
        int b2 = qv0[b].z * sc + zc, b3 = qv0[b].w * sc + zc;
        uint32_t p01 = prmt((uint32_t)b0, (uint32_t)b1, 0x0040);
        uint32_t p23 = prmt((uint32_t)b2, (uint32_t)b3, 0x0040);
        uint32_t pk0 = prmt(p01, p23, 0x5410);
        int c0 = qv1[b].x * sc + zc, c1 = qv1[b].y * sc + zc;
        int c2 = qv1[b].z * sc + zc, c3 = qv1[b].w * sc + zc;
        uint32_t q01 = prmt((uint32_t)c0, (uint32_t)c1, 0x0040);
        uint32_t q23 = prmt((uint32_t)c2, (uint32_t)c3, 0x0040);
        uint32_t pk1 = prmt(q01, q23, 0x5410);
        *(uint2*)(&Bs[s][nl * kPad + seg * 8]) = make_uint2(pk0, pk1);
    };

    // ---- consumer mapping (validated): warp -> (m-tile, n-tile) ----
    const int mt = warp & 3;       // 16-row m-tile
    const int nt = warp >> 2;      // 8-col n-tile
    const uint32_t a_off = (uint32_t)((mt * 16 + (lane & 7) + ((lane >> 3) & 1) * 8) * kPad
                                      + ((lane >> 4) & 1) * 16);
    const uint32_t b_off = (uint32_t)((nt * 8 + (lane & 7)) * kPad + (lane >> 3) * 16);
    int acc[2][4] = {};   // two independent chains (k-halves of each chunk)

    // ---- prologue: chunks 0 and 1 in regs; stage 0 built (exactly as R6) ----
    ldg_chunk(0);
    ldg_chunk(1);
    cp_a(0, 0);
    dequant_sts(0, 0);
    cp_wait_all();
    __syncthreads();

    for (int c = 0; c < kChunks; ++c) {
        const int s = c & 1;
        if (c + 2 < kChunks) ldg_chunk(c + 2);
        if (c + 1 < kChunks) cp_a(c + 1, s ^ 1);

        const uint32_t abase = smem_u32(&As[s][0]) + a_off;
        const uint32_t bbase = smem_u32(&Bs[s][0]) + b_off;
#pragma unroll
        for (int kp = 0; kp < 2; ++kp) {
            uint32_t bf[4];
            ldmatrix_x4(bf, bbase + kp * 64);
#pragma unroll
            for (int k2 = 0; k2 < 2; ++k2) {
                uint32_t a[4];
                ldmatrix_x4(a, abase + (kp * 2 + k2) * 32);
                mma_s8(acc[kp], a[0], a[1], a[2], a[3], bf[k2 * 2], bf[k2 * 2 + 1]);
            }
        }

        if (c + 1 < kChunks) dequant_sts(c + 1, s ^ 1);
        cp_wait_all();
        __syncthreads();
    }

    // ---- store int32 partials for this split (exact) ----
    const int r = mt * 16 + (lane >> 2);
    const int n = n0 + nt * 8 + (lane & 3) * 2;
    const int a0 = acc[0][0] + acc[1][0], a1 = acc[0][1] + acc[1][1];
    const int a2 = acc[0][2] + acc[1][2], a3 = acc[0][3] + acc[1][3];
    int* pbase = &g_part[split][0];
    *(int2*)(pbase + (size_t)r * kN + n) = make_int2(a0, a1);
    *(int2*)(pbase + (size_t)(r + 8) * kN + n) = make_int2(a2, a3);
}

// ---------------- epilogue: sum splits, scale, bias (validated R4) ----------------
__global__ void epilogue_kernel(const float* __restrict__ input_scales,
                                const float* __restrict__ s1_scales,
                                const float* __restrict__ bias,
                                float* __restrict__ out) {
    int idx = blockIdx.x * blockDim.x + threadIdx.x;  // quad index over M*N/4
    int m = idx / (kN / 4);
    int n = (idx - m * (kN / 4)) * 4;
    int4 p0 = *(const int4*)&g_part[0][(size_t)m * kN + n];
    int4 p1 = *(const int4*)&g_part[1][(size_t)m * kN + n];
    float is = input_scales[m];
    float4 s = *(const float4*)(s1_scales + n);
    float4 b = *(const float4*)(bias + n);
    float4 o;
    o.x = (float)(p0.x + p1.x) * is * s.x + b.x;
    o.y = (float)(p0.y + p1.y) * is * s.y + b.y;
    o.z = (float)(p0.z + p1.z) * is * s.z + b.z;
    o.w = (float)(p0.w + p1.w) * is * s.w + b.w;
    *(float4*)(out + (size_t)m * kN + n) = o;
}

extern "C" void kernel_launch(void* const* d_in, const int* in_sizes, int n_in,
                              void* d_out, int out_size) {
    const int* x           = (const int*)d_in[0];
    const float* in_scales = (const float*)d_in[1];
    // d_in[2] = input_sum (unused)
    const int* qweight     = (const int*)d_in[3];
    const int* s2_scales   = (const int*)d_in[4];
    const int* s2_zeros    = (const int*)d_in[5];
    const float* s1_scales = (const float*)d_in[6];
    const float* bias      = (const float*)d_in[7];
    float* out             = (float*)d_out;
    (void)in_sizes; (void)n_in; (void)out_size;

    pack_x_kernel<<<(kM * kK / 4) / kThreads, kThreads>>>(x);
    w4a8_gemm<<<kTiles * kSplit, kThreads>>>(qweight, s2_scales, s2_zeros);
    epilogue_kernel<<<(kM * kN / 4) / 512, 512>>>(in_scales, s1_scales, bias, out);
}